// round 4
// baseline (speedup 1.0000x reference)
#include <cuda_runtime.h>

#define D 128
#define MAX_DST 65536

// ---- scratch (static __device__ per allocation rules) ----
__device__ int   g_off[MAX_DST + 1];
__device__ float g_hn[(size_t)MAX_DST * D];   // 32 MB: mean-aggregated neighbor features

// ============================================================
// Kernel 0: CSR row offsets from SORTED dst_idx (no atomics).
// g_off[d] = first edge index e with dst[e] >= d.
// ============================================================
__global__ void build_offsets_kernel(const int* __restrict__ dst, int n_edges, int n_dst) {
    int e = blockIdx.x * blockDim.x + threadIdx.x;
    if (e > n_edges) return;
    if (e == 0) {
        int d1 = dst[0];
        for (int d = 0; d <= d1; ++d) g_off[d] = 0;
    } else if (e == n_edges) {
        int d0 = dst[n_edges - 1];
        for (int d = d0 + 1; d <= n_dst; ++d) g_off[d] = n_edges;
    } else {
        int d0 = dst[e - 1];
        int d1 = dst[e];
        for (int d = d0 + 1; d <= d1; ++d) g_off[d] = e;
    }
}

// ============================================================
// Kernel 1: segment-mean aggregation. One warp per dst row.
// Lane covers 4 columns (float4). 4-edge unroll for MLP.
// ============================================================
__global__ void aggregate_kernel(const float* __restrict__ feat,
                                 const int* __restrict__ src,
                                 int n_dst) {
    int warp = (int)((blockIdx.x * blockDim.x + threadIdx.x) >> 5);
    int lane = threadIdx.x & 31;
    if (warp >= n_dst) return;

    int lo = g_off[warp];
    int hi = g_off[warp + 1];

    const float4* __restrict__ fbase = (const float4*)feat;   // 32 float4 per row
    float ax = 0.f, ay = 0.f, az = 0.f, aw = 0.f;

    int e = lo;
    for (; e + 4 <= hi; e += 4) {
        int s0 = src[e + 0];
        int s1 = src[e + 1];
        int s2 = src[e + 2];
        int s3 = src[e + 3];
        float4 v0 = fbase[s0 * 32 + lane];
        float4 v1 = fbase[s1 * 32 + lane];
        float4 v2 = fbase[s2 * 32 + lane];
        float4 v3 = fbase[s3 * 32 + lane];
        ax += (v0.x + v1.x) + (v2.x + v3.x);
        ay += (v0.y + v1.y) + (v2.y + v3.y);
        az += (v0.z + v1.z) + (v2.z + v3.z);
        aw += (v0.w + v1.w) + (v2.w + v3.w);
    }
    for (; e < hi; ++e) {
        float4 v = fbase[src[e] * 32 + lane];
        ax += v.x; ay += v.y; az += v.z; aw += v.w;
    }

    float invd = 1.0f / fmaxf((float)(hi - lo), 1.0f);
    float4 o;
    o.x = ax * invd; o.y = ay * invd; o.z = az * invd; o.w = aw * invd;
    ((float4*)g_hn)[warp * 32 + lane] = o;
}

// ============================================================
// Kernel 2: fused GEMM
//   out = [feat[:n_dst] | g_hn] @ [W_self ; W_neigh] + (b_self + b_neigh)
//   M = n_dst, N = 128, K = 256.
// Tile: BM=128, BN=128, BK=32; 256 threads; 8x8 micro-tile.
// Inner product via packed fma.rn.f32x2 (2 MACs / lane-instr).
// ============================================================
#define BM 128
#define BN 128
#define BK 32

__device__ __forceinline__ unsigned long long pack_dup(float x) {
    unsigned long long r;
    asm("mov.b64 %0, {%1, %1};" : "=l"(r) : "r"(__float_as_uint(x)));
    return r;
}
__device__ __forceinline__ unsigned long long pack2(float x, float y) {
    unsigned long long r;
    asm("mov.b64 %0, {%1, %2};" : "=l"(r) : "r"(__float_as_uint(x)), "r"(__float_as_uint(y)));
    return r;
}
__device__ __forceinline__ void ffma2(unsigned long long& c, unsigned long long a, unsigned long long b) {
    asm("fma.rn.f32x2 %0, %1, %2, %0;" : "+l"(c) : "l"(a), "l"(b));
}
__device__ __forceinline__ float2 unpack2(unsigned long long v) {
    unsigned lo, hi;
    asm("mov.b64 {%0, %1}, %2;" : "=r"(lo), "=r"(hi) : "l"(v));
    return make_float2(__uint_as_float(lo), __uint_as_float(hi));
}

__global__ __launch_bounds__(256) void gemm_fused_kernel(
    const float* __restrict__ feat,
    const float* __restrict__ Wself,
    const float* __restrict__ bself,
    const float* __restrict__ Wneigh,
    const float* __restrict__ bneigh,
    float* __restrict__ out) {

    __shared__ float As[BK][BM];   // k-major: As[kk][row]
    __shared__ float Bs[BK][BN];   // Bs[kk][col]

    const int tid  = threadIdx.x;
    const int trow = tid >> 4;     // 0..15 -> rows trow*8..+7
    const int tcol = tid & 15;     // 0..15 -> cols tcol*8..+7
    const int rowBase = blockIdx.x * BM;

    unsigned long long acc[8][4];
#pragma unroll
    for (int i = 0; i < 8; ++i)
#pragma unroll
        for (int j = 0; j < 4; ++j) acc[i][j] = 0ULL;

    for (int c = 0; c < 8; ++c) {       // 8 chunks of K=32 over K'=256
        const float* Asrc = (c < 4) ? feat : g_hn;
        const float* Bsrc = (c < 4) ? Wself : Wneigh;
        const int kbase = (c & 3) * BK;

        // global loads into registers (overlaps previous compute tail)
        float4 aR[4], bR[4];
#pragma unroll
        for (int i = 0; i < 4; ++i) {
            int fa = i * 256 + tid;
            int arow = fa >> 3, ak4 = fa & 7;            // A: 128 rows x 8 float4
            aR[i] = *(const float4*)(Asrc + (size_t)(rowBase + arow) * D + kbase + ak4 * 4);
            int kk = fa >> 5, j4 = fa & 31;              // B: 32 kk x 32 float4
            bR[i] = *(const float4*)(Bsrc + (size_t)(kbase + kk) * D + j4 * 4);
        }

        __syncthreads();    // previous chunk's compute done
#pragma unroll
        for (int i = 0; i < 4; ++i) {
            int fa = i * 256 + tid;
            int arow = fa >> 3, ak4 = fa & 7;
            As[ak4 * 4 + 0][arow] = aR[i].x;
            As[ak4 * 4 + 1][arow] = aR[i].y;
            As[ak4 * 4 + 2][arow] = aR[i].z;
            As[ak4 * 4 + 3][arow] = aR[i].w;
            int kk = fa >> 5, j4 = fa & 31;
            *(float4*)&Bs[kk][j4 * 4] = bR[i];
        }
        __syncthreads();

#pragma unroll 8
        for (int kk = 0; kk < BK; ++kk) {
            float4 a0 = *(const float4*)&As[kk][trow * 8];
            float4 a1 = *(const float4*)&As[kk][trow * 8 + 4];
            float4 b0 = *(const float4*)&Bs[kk][tcol * 8];
            float4 b1 = *(const float4*)&Bs[kk][tcol * 8 + 4];

            unsigned long long ap[8];
            ap[0] = pack_dup(a0.x); ap[1] = pack_dup(a0.y);
            ap[2] = pack_dup(a0.z); ap[3] = pack_dup(a0.w);
            ap[4] = pack_dup(a1.x); ap[5] = pack_dup(a1.y);
            ap[6] = pack_dup(a1.z); ap[7] = pack_dup(a1.w);
            unsigned long long bp[4];
            bp[0] = pack2(b0.x, b0.y); bp[1] = pack2(b0.z, b0.w);
            bp[2] = pack2(b1.x, b1.y); bp[3] = pack2(b1.z, b1.w);

#pragma unroll
            for (int i = 0; i < 8; ++i)
#pragma unroll
                for (int j = 0; j < 4; ++j)
                    ffma2(acc[i][j], ap[i], bp[j]);
        }
    }

    // epilogue: bias add + store
    const int colBase = tcol * 8;
    float bias[8];
#pragma unroll
    for (int jj = 0; jj < 8; ++jj)
        bias[jj] = bself[colBase + jj] + bneigh[colBase + jj];

#pragma unroll
    for (int i = 0; i < 8; ++i) {
        int r = rowBase + trow * 8 + i;
        float2 p0 = unpack2(acc[i][0]);
        float2 p1 = unpack2(acc[i][1]);
        float2 p2 = unpack2(acc[i][2]);
        float2 p3 = unpack2(acc[i][3]);
        float4 w0, w1;
        w0.x = p0.x + bias[0]; w0.y = p0.y + bias[1];
        w0.z = p1.x + bias[2]; w0.w = p1.y + bias[3];
        w1.x = p2.x + bias[4]; w1.y = p2.y + bias[5];
        w1.z = p3.x + bias[6]; w1.w = p3.y + bias[7];
        *(float4*)(out + (size_t)r * D + colBase)     = w0;
        *(float4*)(out + (size_t)r * D + colBase + 4) = w1;
    }
}

// ============================================================
// launch
// ============================================================
extern "C" void kernel_launch(void* const* d_in, const int* in_sizes, int n_in,
                              void* d_out, int out_size) {
    const float* feat   = (const float*)d_in[0];
    const float* Wself  = (const float*)d_in[1];
    const float* bself  = (const float*)d_in[2];
    const float* Wneigh = (const float*)d_in[3];
    const float* bneigh = (const float*)d_in[4];
    const int*   src    = (const int*)d_in[5];
    const int*   dst    = (const int*)d_in[6];
    // d_in[7] (num_row) unused: n_dst derived from out_size

    int n_edges = in_sizes[5];
    int n_dst   = out_size / D;

    // 0) CSR offsets from sorted dst
    {
        int threads = 256;
        int blocks = (n_edges + 1 + threads - 1) / threads;
        build_offsets_kernel<<<blocks, threads>>>(dst, n_edges, n_dst);
    }
    // 1) segment-mean aggregation (one warp / row; 8 warps / block)
    {
        int threads = 256;
        int blocks = (n_dst + 7) / 8;
        aggregate_kernel<<<blocks, threads>>>(feat, src, n_dst);
    }
    // 2) fused single GEMM (K = 256) + bias
    {
        int blocks = n_dst / BM;   // n_dst = 65536 -> 512
        gemm_fused_kernel<<<blocks, 256>>>(feat, Wself, bself, Wneigh, bneigh, (float*)d_out);
    }
}

// round 9
// speedup vs baseline: 1.7760x; 1.7760x over previous
#include <cuda_runtime.h>
#include <cuda_bf16.h>
#include <cstdint>

#define D 128
#define MAX_DST 65536

// ---- scratch (__device__ globals per allocation rules) ----
__device__ int   g_off[MAX_DST + 1];
__device__ __align__(16) float g_hn[(size_t)MAX_DST * D];      // 32 MB mean-aggregated feats
__device__ __align__(16) __nv_bfloat16 g_Wt_hi[2 * 128 * 128]; // [src][n][k] transposed hi
__device__ __align__(16) __nv_bfloat16 g_Wt_lo[2 * 128 * 128]; // [src][n][k] transposed lo
__device__ float g_bsum[128];

// ============================================================
// Kernel 0: CSR offsets from SORTED dst (no atomics) + W prep fused
// ============================================================
__global__ void prep_kernel(const int* __restrict__ dst, int n_edges, int n_dst,
                            const float* __restrict__ Wself, const float* __restrict__ Wneigh,
                            const float* __restrict__ bself, const float* __restrict__ bneigh,
                            int offBlocks) {
    if ((int)blockIdx.x >= offBlocks) {
        int t = (blockIdx.x - offBlocks) * blockDim.x + threadIdx.x;  // 0..4095
        for (int o = t; o < 2 * 128 * 128; o += 16 * 256) {
            int s = o >> 14, rem = o & 16383;
            int n = rem >> 7, k = rem & 127;
            const float* W = s ? Wneigh : Wself;
            float x = W[k * 128 + n];
            __nv_bfloat16 h = __float2bfloat16(x);
            g_Wt_hi[o] = h;
            g_Wt_lo[o] = __float2bfloat16(x - __bfloat162float(h));
        }
        if ((int)blockIdx.x == offBlocks && threadIdx.x < 128)
            g_bsum[threadIdx.x] = bself[threadIdx.x] + bneigh[threadIdx.x];
        return;
    }
    int e = blockIdx.x * blockDim.x + threadIdx.x;
    if (e > n_edges) return;
    if (e == 0) {
        int d1 = dst[0];
        for (int d = 0; d <= d1; ++d) g_off[d] = 0;
    } else if (e == n_edges) {
        int d0 = dst[n_edges - 1];
        for (int d = d0 + 1; d <= n_dst; ++d) g_off[d] = n_edges;
    } else {
        int d0 = dst[e - 1];
        int d1 = dst[e];
        for (int d = d0 + 1; d <= d1; ++d) g_off[d] = e;
    }
}

// ============================================================
// Kernel 1: segment-mean aggregation. One warp per dst row.
// ============================================================
__global__ void aggregate_kernel(const float* __restrict__ feat,
                                 const int* __restrict__ src,
                                 int n_dst) {
    int warp = (int)((blockIdx.x * blockDim.x + threadIdx.x) >> 5);
    int lane = threadIdx.x & 31;
    if (warp >= n_dst) return;

    int lo = g_off[warp];
    int hi = g_off[warp + 1];

    const float4* __restrict__ fbase = (const float4*)feat;
    float ax = 0.f, ay = 0.f, az = 0.f, aw = 0.f;

    int e = lo;
    for (; e + 4 <= hi; e += 4) {
        int s0 = src[e + 0];
        int s1 = src[e + 1];
        int s2 = src[e + 2];
        int s3 = src[e + 3];
        float4 v0 = fbase[s0 * 32 + lane];
        float4 v1 = fbase[s1 * 32 + lane];
        float4 v2 = fbase[s2 * 32 + lane];
        float4 v3 = fbase[s3 * 32 + lane];
        ax += (v0.x + v1.x) + (v2.x + v3.x);
        ay += (v0.y + v1.y) + (v2.y + v3.y);
        az += (v0.z + v1.z) + (v2.z + v3.z);
        aw += (v0.w + v1.w) + (v2.w + v3.w);
    }
    for (; e < hi; ++e) {
        float4 v = fbase[src[e] * 32 + lane];
        ax += v.x; ay += v.y; az += v.z; aw += v.w;
    }

    float invd = 1.0f / fmaxf((float)(hi - lo), 1.0f);
    float4 o;
    o.x = ax * invd; o.y = ay * invd; o.z = az * invd; o.w = aw * invd;
    ((float4*)g_hn)[warp * 32 + lane] = o;
}

// ============================================================
// Kernel 2: mma.sync (HMMA) bf16-split GEMM
//   out = [feat[:n_dst] | g_hn] @ [W_self ; W_neigh] + (b_self+b_neigh)
//   CTA tile 128x128, 8 warps in 4(m)x2(n) grid, warp tile 32x64.
//   8 phases of K=32 (2 sources x 4 k-chunks). Per phase: A fp32->bf16
//   hi/lo into SMEM (row-major, 80B stride = conflict-free + 16B-aligned),
//   W copied pre-split. 3 products per (m16,n8,k16): hihi, hilo, lohi.
// ============================================================
#define AST 40                     // smem row stride in bf16 (80 B)
#define S_BIAS 0
#define S_A_HI 512
#define S_A_LO (512 + 10240)
#define S_W_HI (512 + 20480)
#define S_W_LO (512 + 30720)
#define S_TOTAL (512 + 40960)      // 41472 B static smem

__device__ __forceinline__ uint32_t pack_bf16_hi(float a, float b, uint32_t& lo_out) {
    __nv_bfloat16 ha = __float2bfloat16(a);
    __nv_bfloat16 hb = __float2bfloat16(b);
    __nv_bfloat16 la = __float2bfloat16(a - __bfloat162float(ha));
    __nv_bfloat16 lb = __float2bfloat16(b - __bfloat162float(hb));
    lo_out = (uint32_t)__bfloat16_as_ushort(la) | ((uint32_t)__bfloat16_as_ushort(lb) << 16);
    return (uint32_t)__bfloat16_as_ushort(ha) | ((uint32_t)__bfloat16_as_ushort(hb) << 16);
}

__device__ __forceinline__ void mma16816(float* c, const uint32_t* a, const uint32_t* b) {
    asm volatile(
        "mma.sync.aligned.m16n8k16.row.col.f32.bf16.bf16.f32 "
        "{%0,%1,%2,%3}, {%4,%5,%6,%7}, {%8,%9}, {%0,%1,%2,%3};"
        : "+f"(c[0]), "+f"(c[1]), "+f"(c[2]), "+f"(c[3])
        : "r"(a[0]), "r"(a[1]), "r"(a[2]), "r"(a[3]), "r"(b[0]), "r"(b[1]));
}

__global__ __launch_bounds__(256) void gemm_mma_kernel(
    const float* __restrict__ feat, float* __restrict__ out) {

    __shared__ __align__(16) char smem[S_TOTAL];

    const int tid  = threadIdx.x;
    const int wid  = tid >> 5;
    const int lane = tid & 31;
    const int wm   = wid >> 1;        // 0..3 -> m rows [wm*32, +32)
    const int wn   = wid & 1;         // 0..1 -> n cols [wn*64, +64)
    const int rowBase = blockIdx.x * 128;

    if (tid < 128) ((float*)(smem + S_BIAS))[tid] = g_bsum[tid];

    float acc[2][8][4];
#pragma unroll
    for (int mt = 0; mt < 2; ++mt)
#pragma unroll
        for (int nt = 0; nt < 8; ++nt)
#pragma unroll
            for (int q = 0; q < 4; ++q) acc[mt][nt][q] = 0.f;

    const int lrow = lane >> 2;       // 0..7
    const int lkp  = lane & 3;        // 0..3 -> k pair (lkp*2)

    for (int ph = 0; ph < 8; ++ph) {
        const int s = ph >> 2;                // 0=feat, 1=g_hn
        const int kbase = (ph & 3) * 32;
        const float* Asrc = s ? (const float*)g_hn : feat;

        __syncthreads();   // previous phase's compute done with SMEM

        // ---- stage A: 128 rows x 32 k, fp32 -> bf16 hi/lo ----
#pragma unroll
        for (int i = 0; i < 2; ++i) {
            int c = tid + i * 256;            // 512 chunks of 8 k
            int r = c >> 2, kc = c & 3;
            const float4* p = (const float4*)(Asrc + (size_t)(rowBase + r) * D + kbase + kc * 8);
            float4 x0 = p[0], x1 = p[1];
            uint32_t h0, h1, h2, h3, l0, l1, l2, l3;
            h0 = pack_bf16_hi(x0.x, x0.y, l0);
            h1 = pack_bf16_hi(x0.z, x0.w, l1);
            h2 = pack_bf16_hi(x1.x, x1.y, l2);
            h3 = pack_bf16_hi(x1.z, x1.w, l3);
            uint32_t off = r * (AST * 2) + kc * 16;
            *(uint4*)(smem + S_A_HI + off) = make_uint4(h0, h1, h2, h3);
            *(uint4*)(smem + S_A_LO + off) = make_uint4(l0, l1, l2, l3);
        }
        // ---- stage W: 128 n-rows x 32 k (pre-split bf16) ----
#pragma unroll
        for (int i = 0; i < 2; ++i) {
            int c = tid + i * 256;
            int n = c >> 2, kc = c & 3;
            size_t go = ((size_t)(s * 128 + n)) * 128 + kbase + kc * 8;
            uint4 wh = *(const uint4*)(g_Wt_hi + go);
            uint4 wl = *(const uint4*)(g_Wt_lo + go);
            uint32_t off = n * (AST * 2) + kc * 16;
            *(uint4*)(smem + S_W_HI + off) = wh;
            *(uint4*)(smem + S_W_LO + off) = wl;
        }
        __syncthreads();

        // ---- compute: 2 k16-steps ----
#pragma unroll
        for (int k16 = 0; k16 < 2; ++k16) {
            const uint32_t kb = k16 * 32 + lkp * 4;   // byte offset of this lane's k pair

            // A fragments: 2 m16 subtiles x hi/lo, 4 regs each
            uint32_t a_hi[2][4], a_lo[2][4];
#pragma unroll
            for (int mt = 0; mt < 2; ++mt) {
                uint32_t rb = (wm * 32 + mt * 16 + lrow) * (AST * 2) + kb;
                a_hi[mt][0] = *(const uint32_t*)(smem + S_A_HI + rb);
                a_hi[mt][1] = *(const uint32_t*)(smem + S_A_HI + rb + 8 * (AST * 2));
                a_hi[mt][2] = *(const uint32_t*)(smem + S_A_HI + rb + 16);
                a_hi[mt][3] = *(const uint32_t*)(smem + S_A_HI + rb + 8 * (AST * 2) + 16);
                a_lo[mt][0] = *(const uint32_t*)(smem + S_A_LO + rb);
                a_lo[mt][1] = *(const uint32_t*)(smem + S_A_LO + rb + 8 * (AST * 2));
                a_lo[mt][2] = *(const uint32_t*)(smem + S_A_LO + rb + 16);
                a_lo[mt][3] = *(const uint32_t*)(smem + S_A_LO + rb + 8 * (AST * 2) + 16);
            }

#pragma unroll
            for (int nt = 0; nt < 8; ++nt) {
                uint32_t nb = (wn * 64 + nt * 8 + lrow) * (AST * 2) + kb;
                uint32_t b_hi[2], b_lo[2];
                b_hi[0] = *(const uint32_t*)(smem + S_W_HI + nb);
                b_hi[1] = *(const uint32_t*)(smem + S_W_HI + nb + 16);
                b_lo[0] = *(const uint32_t*)(smem + S_W_LO + nb);
                b_lo[1] = *(const uint32_t*)(smem + S_W_LO + nb + 16);
#pragma unroll
                for (int mt = 0; mt < 2; ++mt) {
                    mma16816(acc[mt][nt], a_hi[mt], b_hi);
                    mma16816(acc[mt][nt], a_hi[mt], b_lo);
                    mma16816(acc[mt][nt], a_lo[mt], b_hi);
                }
            }
        }
    }

    // ---- epilogue: bias + store ----
    const float* bias = (const float*)(smem + S_BIAS);
#pragma unroll
    for (int mt = 0; mt < 2; ++mt) {
        int r0 = rowBase + wm * 32 + mt * 16 + lrow;
#pragma unroll
        for (int nt = 0; nt < 8; ++nt) {
            int col = wn * 64 + nt * 8 + lkp * 2;
            float b0 = bias[col], b1 = bias[col + 1];
            float2 v0 = make_float2(acc[mt][nt][0] + b0, acc[mt][nt][1] + b1);
            float2 v1 = make_float2(acc[mt][nt][2] + b0, acc[mt][nt][3] + b1);
            *(float2*)(out + (size_t)r0 * D + col)       = v0;
            *(float2*)(out + (size_t)(r0 + 8) * D + col) = v1;
        }
    }
}

// ============================================================
// launch
// ============================================================
extern "C" void kernel_launch(void* const* d_in, const int* in_sizes, int n_in,
                              void* d_out, int out_size) {
    const float* feat   = (const float*)d_in[0];
    const float* Wself  = (const float*)d_in[1];
    const float* bself  = (const float*)d_in[2];
    const float* Wneigh = (const float*)d_in[3];
    const float* bneigh = (const float*)d_in[4];
    const int*   src    = (const int*)d_in[5];
    const int*   dst    = (const int*)d_in[6];

    int n_edges = in_sizes[5];
    int n_dst   = out_size / D;

    // 0) CSR offsets + W bf16 split/transpose + bias sum (fused)
    {
        int threads = 256;
        int offBlocks = (n_edges + 1 + threads - 1) / threads;
        prep_kernel<<<offBlocks + 16, threads>>>(dst, n_edges, n_dst,
                                                 Wself, Wneigh, bself, bneigh, offBlocks);
    }
    // 1) segment-mean aggregation (one warp / row)
    {
        int threads = 256;
        int blocks = (n_dst + 7) / 8;
        aggregate_kernel<<<blocks, threads>>>(feat, src, n_dst);
    }
    // 2) HMMA tensor-core GEMM + bias (static smem, no attrs needed)
    {
        int blocks = n_dst / 128;   // 512
        gemm_mma_kernel<<<blocks, 256>>>(feat, (float*)d_out);
    }
}